// round 1
// baseline (speedup 1.0000x reference)
#include <cuda_runtime.h>
#include <math.h>

// ---------------------------------------------------------------------------
// Problem constants (PerceiverResampler)
// ---------------------------------------------------------------------------
#define DIMV   1024
#define NDEPTH 6
#define NHEADS 16
#define DHEAD  64
#define INNERV 1024
#define NLAT   64
#define FFV    4096
#define BTV    32          // B*T = 4*8
#define MEDIA  1024        // F*V = 4*256
#define NKV    1088        // MEDIA + NLAT
#define LNEPS  1e-5f

// ---------------------------------------------------------------------------
// Scratch (static device allocations -- allocation-free at runtime)
// ---------------------------------------------------------------------------
__device__ float g_xhat[(size_t)BTV * MEDIA * DIMV];        // 32768 x 1024  (128 MB)
__device__ float g_kvm [(size_t)BTV * MEDIA * 2 * INNERV];  // 32768 x 2048  (256 MB)
__device__ float g_lat [(size_t)BTV * NLAT * DIMV];         // 2048 x 1024
__device__ float g_latn[(size_t)BTV * NLAT * DIMV];         // 2048 x 1024
__device__ float g_qb  [(size_t)BTV * NLAT * INNERV];       // 2048 x 1024
__device__ float g_kvl [(size_t)BTV * NLAT * 2 * INNERV];   // 2048 x 2048
__device__ float g_attn[(size_t)BTV * NLAT * INNERV];       // 2048 x 1024
__device__ float g_ffh [(size_t)BTV * NLAT * FFV];          // 2048 x 4096  (32 MB)

// ---------------------------------------------------------------------------
// lat[bt, n, :] = latents[n, :]
// ---------------------------------------------------------------------------
__global__ void __launch_bounds__(256) init_lat_kernel(
    const float* __restrict__ latents, float* __restrict__ lat)
{
    int idx4 = blockIdx.x * 256 + threadIdx.x;   // 524288 float4 total
    int row  = idx4 >> 8;                        // 256 float4 per row of 1024
    int c4   = idx4 & 255;
    int n    = row & 63;
    float4 v = *(const float4*)(latents + (size_t)n * DIMV + (c4 << 2));
    *(float4*)(lat + ((size_t)row << 10) + (c4 << 2)) = v;
}

// ---------------------------------------------------------------------------
// LayerNorm over rows of length 1024.  g/b may be null (identity affine).
// ---------------------------------------------------------------------------
__global__ void __launch_bounds__(256) ln_kernel(
    const float* __restrict__ in, float* __restrict__ out,
    const float* __restrict__ g, const float* __restrict__ b)
{
    __shared__ float red[2][8];
    size_t row = blockIdx.x;
    const float* x = in + row * DIMV;
    int t = threadIdx.x;

    float4 v = *(const float4*)(x + (t << 2));
    float s  = v.x + v.y + v.z + v.w;
    float ss = v.x*v.x + v.y*v.y + v.z*v.z + v.w*v.w;
    #pragma unroll
    for (int off = 16; off; off >>= 1) {
        s  += __shfl_xor_sync(0xffffffffu, s,  off);
        ss += __shfl_xor_sync(0xffffffffu, ss, off);
    }
    int w = t >> 5, lane = t & 31;
    if (lane == 0) { red[0][w] = s; red[1][w] = ss; }
    __syncthreads();
    if (t == 0) {
        float ts = 0.f, tss = 0.f;
        #pragma unroll
        for (int i = 0; i < 8; i++) { ts += red[0][i]; tss += red[1][i]; }
        red[0][0] = ts; red[1][0] = tss;
    }
    __syncthreads();
    float mean = red[0][0] * (1.f / 1024.f);
    float var  = red[1][0] * (1.f / 1024.f) - mean * mean;
    float inv  = rsqrtf(var + LNEPS);

    float gx = 1.f, gy = 1.f, gz = 1.f, gw = 1.f;
    float bx = 0.f, by = 0.f, bz = 0.f, bw = 0.f;
    if (g) {
        float4 gg = *(const float4*)(g + (t << 2));
        float4 bb = *(const float4*)(b + (t << 2));
        gx = gg.x; gy = gg.y; gz = gg.z; gw = gg.w;
        bx = bb.x; by = bb.y; bz = bb.z; bw = bb.w;
    }
    float4 o;
    o.x = (v.x - mean) * inv * gx + bx;
    o.y = (v.y - mean) * inv * gy + by;
    o.z = (v.z - mean) * inv * gz + bz;
    o.w = (v.w - mean) * inv * gw + bw;
    *(float4*)(out + row * DIMV + (t << 2)) = o;
}

// ---------------------------------------------------------------------------
// Generic fp32 GEMM: C[M,N] = op( A'[M,K] @ B[K,N] (+ resid) )
//   A' = A * aScale[k] + aBias[k]  (optional, fuses per-layer LN affine)
//   resid: optional elementwise add (residual connection)
//   doGelu: exact GELU epilogue
// Block tile 128x128, BK=8, 256 threads, 8x8 per thread, prefetch pipeline.
// All of M,N multiples of 128, K multiple of 8 -- no bounds checks.
// ---------------------------------------------------------------------------
__global__ void __launch_bounds__(256) gemm_kernel(
    const float* __restrict__ A, const float* __restrict__ B,
    float* __restrict__ C,
    int K, int lda, int ldb, int ldc,
    const float* __restrict__ aScale, const float* __restrict__ aBias,
    const float* __restrict__ resid, int doGelu)
{
    __shared__ float As[8][128];
    __shared__ float Bs[8][128];

    const int m0 = blockIdx.y << 7;
    const int n0 = blockIdx.x << 7;
    const int tid  = threadIdx.x;
    const int cRow = tid >> 4;       // 0..15
    const int cCol = tid & 15;       // 0..15

    // load-index assignments
    const int ar = tid >> 1;         // 0..127 (A tile row)
    const int ac = (tid & 1) << 2;   // 0 or 4 (A tile col base)
    const int br = tid >> 5;         // 0..7   (B tile row)
    const int bc = (tid & 31) << 2;  // 0..124 (B tile col base)

    const float* Aptr = A + (size_t)(m0 + ar) * lda + ac;
    const float* Bptr = B + (size_t)br * ldb + n0 + bc;

    float acc[8][8];
    #pragma unroll
    for (int i = 0; i < 8; i++)
        #pragma unroll
        for (int j = 0; j < 8; j++) acc[i][j] = 0.f;

    float4 a4 = *(const float4*)(Aptr);
    float4 b4 = *(const float4*)(Bptr);

    for (int k0 = 0; k0 < K; k0 += 8) {
        float4 av = a4;
        if (aScale) {
            av.x = av.x * aScale[k0 + ac + 0] + aBias[k0 + ac + 0];
            av.y = av.y * aScale[k0 + ac + 1] + aBias[k0 + ac + 1];
            av.z = av.z * aScale[k0 + ac + 2] + aBias[k0 + ac + 2];
            av.w = av.w * aScale[k0 + ac + 3] + aBias[k0 + ac + 3];
        }
        __syncthreads();
        As[ac + 0][ar] = av.x;
        As[ac + 1][ar] = av.y;
        As[ac + 2][ar] = av.z;
        As[ac + 3][ar] = av.w;
        *(float4*)&Bs[br][bc] = b4;
        __syncthreads();

        if (k0 + 8 < K) {   // prefetch next tile while computing
            a4 = *(const float4*)(Aptr + (k0 + 8));
            b4 = *(const float4*)(Bptr + (size_t)(k0 + 8) * ldb);
        }

        #pragma unroll
        for (int kk = 0; kk < 8; kk++) {
            float ra[8], rb[8];
            *(float4*)(ra)     = *(const float4*)(&As[kk][cRow << 3]);
            *(float4*)(ra + 4) = *(const float4*)(&As[kk][(cRow << 3) + 4]);
            *(float4*)(rb)     = *(const float4*)(&Bs[kk][cCol << 3]);
            *(float4*)(rb + 4) = *(const float4*)(&Bs[kk][(cCol << 3) + 4]);
            #pragma unroll
            for (int i = 0; i < 8; i++)
                #pragma unroll
                for (int j = 0; j < 8; j++)
                    acc[i][j] = fmaf(ra[i], rb[j], acc[i][j]);
        }
    }

    #pragma unroll
    for (int i = 0; i < 8; i++) {
        size_t m = (size_t)m0 + (cRow << 3) + i;
        float*       crow = C + m * ldc + n0 + (cCol << 3);
        const float* rrow = resid ? resid + m * ldc + n0 + (cCol << 3) : nullptr;
        #pragma unroll
        for (int j = 0; j < 8; j++) {
            float c = acc[i][j];
            if (rrow)   c += rrow[j];
            if (doGelu) c = 0.5f * c * (1.0f + erff(c * 0.70710678118654752f));
            crow[j] = c;
        }
    }
}

// ---------------------------------------------------------------------------
// Attention: one block per (bt, head).  Queries = 64 latents, KV = 1088
// tokens (1024 media from g_kvm + 64 latents from g_kvl).  Online softmax,
// 34 chunks of 32 tokens.  Output written in [bt*64+n, h*64+d] layout,
// which equals the reference's transpose+reshape.
// ---------------------------------------------------------------------------
__global__ void __launch_bounds__(256) attn_kernel(
    const float* __restrict__ q,   const float* __restrict__ kvm,
    const float* __restrict__ kvl, float* __restrict__ outp)
{
    __shared__ float qs[64][64];
    __shared__ float ks[32][65];
    __shared__ float vs[32][65];
    __shared__ float ps[8][8][32];

    const int bt = blockIdx.x >> 4;
    const int h  = blockIdx.x & 15;
    const int tid  = threadIdx.x;
    const int w    = tid >> 5;
    const int lane = tid & 31;
    const float scale = 0.125f;   // 64^-0.5

    // load Q tile (pre-scaled)
    for (int idx = tid; idx < 1024; idx += 256) {
        int r = idx >> 4;
        int c = (idx & 15) << 2;
        float4 v = *(const float4*)(q + ((size_t)bt * 64 + r) * INNERV + h * DHEAD + c);
        qs[r][c + 0] = v.x * scale;
        qs[r][c + 1] = v.y * scale;
        qs[r][c + 2] = v.z * scale;
        qs[r][c + 3] = v.w * scale;
    }

    float m[8], l[8], o0[8], o1[8];
    #pragma unroll
    for (int i = 0; i < 8; i++) { m[i] = -1e30f; l[i] = 0.f; o0[i] = 0.f; o1[i] = 0.f; }
    __syncthreads();

    for (int chunk = 0; chunk < 34; ++chunk) {
        int j0 = chunk << 5;
        const float* kb;
        if (j0 < 1024) kb = kvm + ((size_t)bt * 1024 + j0) * 2048 + h * DHEAD;
        else           kb = kvl + ((size_t)bt * 64 + (j0 - 1024)) * 2048 + h * DHEAD;

        for (int idx = tid; idx < 512; idx += 256) {
            int r = idx >> 4;
            int c = (idx & 15) << 2;
            const float* src = kb + (size_t)r * 2048 + c;
            float4 kk = *(const float4*)(src);
            ks[r][c + 0] = kk.x; ks[r][c + 1] = kk.y; ks[r][c + 2] = kk.z; ks[r][c + 3] = kk.w;
            float4 vv = *(const float4*)(src + 1024);   // V is cols [1024,2048)
            vs[r][c + 0] = vv.x; vs[r][c + 1] = vv.y; vs[r][c + 2] = vv.z; vs[r][c + 3] = vv.w;
        }
        __syncthreads();

        #pragma unroll
        for (int i = 0; i < 8; i++) {
            int qi = (w << 3) + i;
            float s = 0.f;
            #pragma unroll
            for (int d = 0; d < 64; ++d) s = fmaf(qs[qi][d], ks[lane][d], s);
            float cm = s;
            #pragma unroll
            for (int off = 16; off; off >>= 1)
                cm = fmaxf(cm, __shfl_xor_sync(0xffffffffu, cm, off));
            float mt = fmaxf(m[i], cm);
            float p  = __expf(s - mt);
            float psum = p;
            #pragma unroll
            for (int off = 16; off; off >>= 1)
                psum += __shfl_xor_sync(0xffffffffu, psum, off);
            float corr = __expf(m[i] - mt);
            l[i] = l[i] * corr + psum;
            m[i] = mt;
            o0[i] *= corr;
            o1[i] *= corr;
            ps[w][i][lane] = p;
        }
        __syncwarp();
        #pragma unroll
        for (int i = 0; i < 8; i++) {
            float a0 = o0[i], a1 = o1[i];
            #pragma unroll
            for (int jj = 0; jj < 32; jj++) {
                float p = ps[w][i][jj];
                a0 = fmaf(p, vs[jj][lane],      a0);
                a1 = fmaf(p, vs[jj][lane + 32], a1);
            }
            o0[i] = a0; o1[i] = a1;
        }
        __syncthreads();
    }

    #pragma unroll
    for (int i = 0; i < 8; i++) {
        float inv = 1.f / l[i];
        size_t row = (size_t)bt * 64 + (w << 3) + i;
        outp[row * INNERV + h * DHEAD + lane]      = o0[i] * inv;
        outp[row * INNERV + h * DHEAD + lane + 32] = o1[i] * inv;
    }
}

// ---------------------------------------------------------------------------
// Host orchestration (graph-capturable: kernel launches only)
// ---------------------------------------------------------------------------
extern "C" void kernel_launch(void* const* d_in, const int* in_sizes, int n_in,
                              void* d_out, int out_size)
{
    const float* x       = (const float*)d_in[0];
    const float* latents = (const float*)d_in[1];
    const float* nm_g    = (const float*)d_in[2];
    const float* nm_b    = (const float*)d_in[3];
    const float* nl_g    = (const float*)d_in[4];
    const float* nl_b    = (const float*)d_in[5];
    const float* wq      = (const float*)d_in[6];
    const float* wkv     = (const float*)d_in[7];
    const float* wo      = (const float*)d_in[8];
    const float* ff_g    = (const float*)d_in[9];
    const float* ff_b    = (const float*)d_in[10];
    const float* w1      = (const float*)d_in[11];
    const float* w2      = (const float*)d_in[12];
    const float* fin_g   = (const float*)d_in[13];
    const float* fin_b   = (const float*)d_in[14];

    float *xhat, *kvm, *lat, *latn, *qb, *kvl, *attn, *ffh;
    cudaGetSymbolAddress((void**)&xhat, g_xhat);
    cudaGetSymbolAddress((void**)&kvm,  g_kvm);
    cudaGetSymbolAddress((void**)&lat,  g_lat);
    cudaGetSymbolAddress((void**)&latn, g_latn);
    cudaGetSymbolAddress((void**)&qb,   g_qb);
    cudaGetSymbolAddress((void**)&kvl,  g_kvl);
    cudaGetSymbolAddress((void**)&attn, g_attn);
    cudaGetSymbolAddress((void**)&ffh,  g_ffh);

    // latents broadcast into lat, and xhat = LN(x) without affine (done ONCE:
    // the per-layer affine g_i,b_i is folded into the KV GEMM's A-load).
    init_lat_kernel<<<2048, 256>>>(latents, lat);
    ln_kernel<<<BTV * MEDIA, 256>>>(x, xhat, nullptr, nullptr);

    for (int i = 0; i < NDEPTH; i++) {
        const float* wkv_i = wkv + (size_t)i * DIMV * 2 * INNERV;
        const float* wq_i  = wq  + (size_t)i * DIMV * INNERV;
        const float* wo_i  = wo  + (size_t)i * INNERV * DIMV;
        const float* w1_i  = w1  + (size_t)i * DIMV * FFV;
        const float* w2_i  = w2  + (size_t)i * FFV * DIMV;

        // media KV projection: (xhat * nm_g + nm_b) @ wkv  -> [32768, 2048]
        gemm_kernel<<<dim3(16, 256), 256>>>(xhat, wkv_i, kvm,
            DIMV, DIMV, 2 * INNERV, 2 * INNERV,
            nm_g + (size_t)i * DIMV, nm_b + (size_t)i * DIMV, nullptr, 0);

        // latent LN, Q projection, latent KV projection
        ln_kernel<<<BTV * NLAT, 256>>>(lat, latn,
            nl_g + (size_t)i * DIMV, nl_b + (size_t)i * DIMV);
        gemm_kernel<<<dim3(8, 16), 256>>>(latn, wq_i, qb,
            DIMV, DIMV, INNERV, INNERV, nullptr, nullptr, nullptr, 0);
        gemm_kernel<<<dim3(16, 16), 256>>>(latn, wkv_i, kvl,
            DIMV, DIMV, 2 * INNERV, 2 * INNERV, nullptr, nullptr, nullptr, 0);

        // attention over 1088 KV tokens per (bt, head)
        attn_kernel<<<BTV * NHEADS, 256>>>(qb, kvm, kvl, attn);

        // output projection + residual
        gemm_kernel<<<dim3(8, 16), 256>>>(attn, wo_i, lat,
            INNERV, INNERV, DIMV, DIMV, nullptr, nullptr, lat, 0);

        // feed-forward: lat += W2( gelu( W1( LN(lat) ) ) )
        ln_kernel<<<BTV * NLAT, 256>>>(lat, latn,
            ff_g + (size_t)i * DIMV, ff_b + (size_t)i * DIMV);
        gemm_kernel<<<dim3(32, 16), 256>>>(latn, w1_i, ffh,
            DIMV, DIMV, FFV, FFV, nullptr, nullptr, nullptr, 1);
        gemm_kernel<<<dim3(8, 16), 256>>>(ffh, w2_i, lat,
            FFV, FFV, DIMV, DIMV, nullptr, nullptr, lat, 0);
    }

    // final LN straight into d_out [4,8,64,1024]
    ln_kernel<<<BTV * NLAT, 256>>>(lat, (float*)d_out, fin_g, fin_b);
}

// round 3
// speedup vs baseline: 3.2663x; 3.2663x over previous
#include <cuda_runtime.h>
#include <math.h>
#include <cstdint>

// ---------------------------------------------------------------------------
// Problem constants (PerceiverResampler)
// ---------------------------------------------------------------------------
#define DIMV   1024
#define NDEPTH 6
#define NHEADS 16
#define DHEAD  64
#define INNERV 1024
#define NLAT   64
#define FFV    4096
#define BTV    32
#define MEDIA  1024
#define LNEPS  1e-5f

// ---------------------------------------------------------------------------
// Scratch (static device allocations)
// ---------------------------------------------------------------------------
__device__ float g_xhat[(size_t)BTV * MEDIA * DIMV];
__device__ float g_kvm [(size_t)BTV * MEDIA * 2 * INNERV];
__device__ float g_lat [(size_t)BTV * NLAT * DIMV];
__device__ float g_latn[(size_t)BTV * NLAT * DIMV];
__device__ float g_qb  [(size_t)BTV * NLAT * INNERV];
__device__ float g_kvl [(size_t)BTV * NLAT * 2 * INNERV];
__device__ float g_attn[(size_t)BTV * NLAT * INNERV];
__device__ float g_ffh [(size_t)BTV * NLAT * FFV];
// transposed tf32-rounded weights: [N, K] K-major
__device__ float g_wqT  [(size_t)NDEPTH * INNERV * DIMV];
__device__ float g_wkvT [(size_t)NDEPTH * 2 * INNERV * DIMV];   // scaled by nm_g (for media KV)
__device__ float g_wkvTl[(size_t)NDEPTH * 2 * INNERV * DIMV];   // plain (for latent KV)
__device__ float g_woT  [(size_t)NDEPTH * DIMV * INNERV];
__device__ float g_w1T  [(size_t)NDEPTH * FFV * DIMV];
__device__ float g_w2T  [(size_t)NDEPTH * DIMV * FFV];
__device__ float g_kvbias[(size_t)NDEPTH * 2 * INNERV];         // nm_b @ wkv

// ---------------------------------------------------------------------------
// helpers
// ---------------------------------------------------------------------------
__device__ __forceinline__ uint32_t smem_u32(const void* p) {
    uint32_t a;
    asm("{ .reg .u64 t; cvta.to.shared.u64 t, %1; cvt.u32.u64 %0, t; }"
        : "=r"(a) : "l"(p));
    return a;
}
__device__ __forceinline__ float tf32r(float x) {
    uint32_t u;
    asm("cvt.rna.tf32.f32 %0, %1;" : "=r"(u) : "f"(x));
    return __uint_as_float(u);
}
__device__ __forceinline__ void cp_async16(uint32_t dst, const void* src) {
    asm volatile("cp.async.cg.shared.global [%0], [%1], 16;" :: "r"(dst), "l"(src));
}
__device__ __forceinline__ void cp_commit() {
    asm volatile("cp.async.commit_group;" ::: "memory");
}
__device__ __forceinline__ void cp_wait1() {
    asm volatile("cp.async.wait_group 1;" ::: "memory");
}
__device__ __forceinline__ void cp_wait0() {
    asm volatile("cp.async.wait_group 0;" ::: "memory");
}
__device__ __forceinline__ void mma_tf32(float& c0, float& c1, float& c2, float& c3,
                                         uint32_t a0, uint32_t a1, uint32_t a2, uint32_t a3,
                                         uint32_t b0, uint32_t b1) {
    asm volatile(
        "mma.sync.aligned.m16n8k8.row.col.f32.tf32.tf32.f32 "
        "{%0,%1,%2,%3}, {%4,%5,%6,%7}, {%8,%9}, {%0,%1,%2,%3};"
        : "+f"(c0), "+f"(c1), "+f"(c2), "+f"(c3)
        : "r"(a0), "r"(a1), "r"(a2), "r"(a3), "r"(b0), "r"(b1));
}
__device__ __forceinline__ float gelu_exact(float x) {
    return 0.5f * x * (1.0f + erff(x * 0.70710678118654752f));
}

// ---------------------------------------------------------------------------
// Weight transpose + tf32 pre-round (+ optional per-k scale):
//   out[N,K] = tf32( in[K,N] * (scale ? scale[k] : 1) )
// ---------------------------------------------------------------------------
__global__ void __launch_bounds__(256) wtrans_kernel(
    const float* __restrict__ in, float* __restrict__ out, int K, int N,
    const float* __restrict__ scale)
{
    __shared__ float t[32][33];
    int n0 = blockIdx.x << 5, k0 = blockIdx.y << 5;
    int tx = threadIdx.x & 31, ty = threadIdx.x >> 5;   // 32 x 8
    #pragma unroll
    for (int p = 0; p < 4; p++) {
        int k = ty + 8 * p;
        float s = scale ? scale[k0 + k] : 1.f;
        t[k][tx] = tf32r(in[(size_t)(k0 + k) * N + n0 + tx] * s);
    }
    __syncthreads();
    #pragma unroll
    for (int p = 0; p < 4; p++) {
        int n = ty + 8 * p;
        out[(size_t)(n0 + n) * K + k0 + tx] = t[tx][n];
    }
}

// ---------------------------------------------------------------------------
// bias[n] = sum_k b[k] * W[k,N-major][n]   (coalesced over n)
// ---------------------------------------------------------------------------
__global__ void __launch_bounds__(256) bias_kernel(
    const float* __restrict__ b, const float* __restrict__ W,
    float* __restrict__ out, int K, int N)
{
    int n = blockIdx.x * 256 + threadIdx.x;
    float s = 0.f;
    for (int k = 0; k < K; k++) s = fmaf(b[k], W[(size_t)k * N + n], s);
    out[n] = s;
}

// ---------------------------------------------------------------------------
// lat broadcast
// ---------------------------------------------------------------------------
__global__ void __launch_bounds__(256) init_lat_kernel(
    const float* __restrict__ latents, float* __restrict__ lat)
{
    int idx4 = blockIdx.x * 256 + threadIdx.x;
    int row  = idx4 >> 8;
    int c4   = idx4 & 255;
    int n    = row & 63;
    float4 v = *(const float4*)(latents + (size_t)n * DIMV + (c4 << 2));
    *(float4*)(lat + ((size_t)row << 10) + (c4 << 2)) = v;
}

// ---------------------------------------------------------------------------
// LayerNorm rows of 1024.  doRound: tf32-round output (for GEMM A operands).
// ---------------------------------------------------------------------------
__global__ void __launch_bounds__(256) ln_kernel(
    const float* __restrict__ in, float* __restrict__ out,
    const float* __restrict__ g, const float* __restrict__ b, int doRound)
{
    __shared__ float red[2][8];
    size_t row = blockIdx.x;
    const float* x = in + row * DIMV;
    int t = threadIdx.x;

    float4 v = *(const float4*)(x + (t << 2));
    float s  = v.x + v.y + v.z + v.w;
    float ss = v.x*v.x + v.y*v.y + v.z*v.z + v.w*v.w;
    #pragma unroll
    for (int off = 16; off; off >>= 1) {
        s  += __shfl_xor_sync(0xffffffffu, s,  off);
        ss += __shfl_xor_sync(0xffffffffu, ss, off);
    }
    int w = t >> 5, lane = t & 31;
    if (lane == 0) { red[0][w] = s; red[1][w] = ss; }
    __syncthreads();
    if (t == 0) {
        float ts = 0.f, tss = 0.f;
        #pragma unroll
        for (int i = 0; i < 8; i++) { ts += red[0][i]; tss += red[1][i]; }
        red[0][0] = ts; red[1][0] = tss;
    }
    __syncthreads();
    float mean = red[0][0] * (1.f / 1024.f);
    float var  = red[1][0] * (1.f / 1024.f) - mean * mean;
    float inv  = rsqrtf(var + LNEPS);

    float gx = 1.f, gy = 1.f, gz = 1.f, gw = 1.f;
    float bx = 0.f, by = 0.f, bz = 0.f, bw = 0.f;
    if (g) {
        float4 gg = *(const float4*)(g + (t << 2));
        float4 bb = *(const float4*)(b + (t << 2));
        gx = gg.x; gy = gg.y; gz = gg.z; gw = gg.w;
        bx = bb.x; by = bb.y; bz = bb.z; bw = bb.w;
    }
    float4 o;
    o.x = (v.x - mean) * inv * gx + bx;
    o.y = (v.y - mean) * inv * gy + by;
    o.z = (v.z - mean) * inv * gz + bz;
    o.w = (v.w - mean) * inv * gw + bw;
    if (doRound) {
        o.x = tf32r(o.x); o.y = tf32r(o.y); o.z = tf32r(o.z); o.w = tf32r(o.w);
    }
    *(float4*)(out + row * DIMV + (t << 2)) = o;
}

// ---------------------------------------------------------------------------
// tf32 mma.sync GEMM:  C[M,N] = op( A[M,K] @ BT[N,K]^T (+bias[n]) (+resid) )
//   A, BT already tf32-rounded.  Tile 128x128, BK=32, 8 warps (2x4),
//   warp tile 64x32 (4x4 m16n8k8 atoms), cp.async double-buffered.
// ---------------------------------------------------------------------------
#define PADK 36
__global__ void __launch_bounds__(256, 2) gemm_mma(
    const float* __restrict__ A, const float* __restrict__ BT, float* __restrict__ C,
    int K, int lda, int ldc,
    const float* __restrict__ bias, const float* __restrict__ resid,
    int doGelu, int doRound)
{
    extern __shared__ float sm[];
    // layout: As[2][128][PADK], Bs[2][128][PADK]
    float* As = sm;
    float* Bs = sm + 2 * 128 * PADK;
    const uint32_t asb = smem_u32(As);
    const uint32_t bsb = smem_u32(Bs);

    const int tid  = threadIdx.x;
    const int wid  = tid >> 5;
    const int lane = tid & 31;
    const int wm   = wid >> 2;          // 0..1
    const int wn   = wid & 3;           // 0..3
    const int g    = lane >> 2;         // 0..7
    const int t    = lane & 3;          // 0..3
    const int m0   = blockIdx.y << 7;
    const int n0   = blockIdx.x << 7;
    const int NK   = K >> 5;

    // global load indexing: 1024 float4 per tile, 4 per thread
    const int lrow = tid >> 1;              // base pattern
    // each thread handles rows {tid>>1 with p stepping}: use idx = p*256+tid
    float acc[4][4][4];
    #pragma unroll
    for (int i = 0; i < 4; i++)
        #pragma unroll
        for (int j = 0; j < 4; j++)
            #pragma unroll
            for (int r = 0; r < 4; r++) acc[i][j][r] = 0.f;
    (void)lrow;

    auto load_tile = [&](int kt, int buf) {
        const int kg = kt << 5;
        #pragma unroll
        for (int p = 0; p < 4; p++) {
            int idx = p * 256 + tid;
            int row = idx >> 3;
            int c4  = (idx & 7) << 2;
            cp_async16(asb + ((buf * 128 + row) * PADK + c4) * 4,
                       A + (size_t)(m0 + row) * lda + kg + c4);
            cp_async16(bsb + ((buf * 128 + row) * PADK + c4) * 4,
                       BT + (size_t)(n0 + row) * K + kg + c4);
        }
    };

    load_tile(0, 0);
    cp_commit();

    for (int kt = 0; kt < NK; kt++) {
        const int buf = kt & 1;
        if (kt + 1 < NK) {
            load_tile(kt + 1, buf ^ 1);
            cp_commit();
            cp_wait1();
        } else {
            cp_wait0();
        }
        __syncthreads();

        const float* Ab = As + (buf * 128) * PADK;
        const float* Bb = Bs + (buf * 128) * PADK;
        #pragma unroll
        for (int ks = 0; ks < 4; ks++) {
            const int kk = ks << 3;
            uint32_t af[4][4], bf[4][2];
            #pragma unroll
            for (int i = 0; i < 4; i++) {
                const float* ap = Ab + (size_t)(wm * 64 + i * 16 + g) * PADK + kk + t;
                af[i][0] = __float_as_uint(ap[0]);
                af[i][1] = __float_as_uint(ap[8 * PADK]);
                af[i][2] = __float_as_uint(ap[4]);
                af[i][3] = __float_as_uint(ap[8 * PADK + 4]);
            }
            #pragma unroll
            for (int j = 0; j < 4; j++) {
                const float* bp = Bb + (size_t)(wn * 32 + j * 8 + g) * PADK + kk + t;
                bf[j][0] = __float_as_uint(bp[0]);
                bf[j][1] = __float_as_uint(bp[4]);
            }
            #pragma unroll
            for (int i = 0; i < 4; i++)
                #pragma unroll
                for (int j = 0; j < 4; j++)
                    mma_tf32(acc[i][j][0], acc[i][j][1], acc[i][j][2], acc[i][j][3],
                             af[i][0], af[i][1], af[i][2], af[i][3],
                             bf[j][0], bf[j][1]);
        }
        __syncthreads();
    }

    // epilogue
    #pragma unroll
    for (int i = 0; i < 4; i++) {
        int mrow = m0 + wm * 64 + i * 16 + g;
        #pragma unroll
        for (int j = 0; j < 4; j++) {
            int ncol = n0 + wn * 32 + j * 8 + 2 * t;
            #pragma unroll
            for (int half = 0; half < 2; half++) {
                int mr = mrow + half * 8;
                float c0 = acc[i][j][2 * half + 0];
                float c1 = acc[i][j][2 * half + 1];
                if (bias) {
                    float2 bv = *(const float2*)(bias + ncol);
                    c0 += bv.x; c1 += bv.y;
                }
                if (resid) {
                    float2 rv = *(const float2*)(resid + (size_t)mr * ldc + ncol);
                    c0 += rv.x; c1 += rv.y;
                }
                if (doGelu) { c0 = gelu_exact(c0); c1 = gelu_exact(c1); }
                if (doRound) { c0 = tf32r(c0); c1 = tf32r(c1); }
                float2 o; o.x = c0; o.y = c1;
                *(float2*)(C + (size_t)mr * ldc + ncol) = o;
            }
        }
    }
}

// ---------------------------------------------------------------------------
// Attention (fp32 SIMT).  Output tf32-rounded (feeds wo GEMM).
// ---------------------------------------------------------------------------
__global__ void __launch_bounds__(256) attn_kernel(
    const float* __restrict__ q,   const float* __restrict__ kvm,
    const float* __restrict__ kvl, float* __restrict__ outp)
{
    __shared__ float qs[64][64];
    __shared__ float ks[32][65];
    __shared__ float vs[32][65];
    __shared__ float ps[8][8][32];

    const int bt = blockIdx.x >> 4;
    const int h  = blockIdx.x & 15;
    const int tid  = threadIdx.x;
    const int w    = tid >> 5;
    const int lane = tid & 31;
    const float scale = 0.125f;

    for (int idx = tid; idx < 1024; idx += 256) {
        int r = idx >> 4;
        int c = (idx & 15) << 2;
        float4 v = *(const float4*)(q + ((size_t)bt * 64 + r) * INNERV + h * DHEAD + c);
        qs[r][c + 0] = v.x * scale;
        qs[r][c + 1] = v.y * scale;
        qs[r][c + 2] = v.z * scale;
        qs[r][c + 3] = v.w * scale;
    }

    float m[8], l[8], o0[8], o1[8];
    #pragma unroll
    for (int i = 0; i < 8; i++) { m[i] = -1e30f; l[i] = 0.f; o0[i] = 0.f; o1[i] = 0.f; }
    __syncthreads();

    for (int chunk = 0; chunk < 34; ++chunk) {
        int j0 = chunk << 5;
        const float* kb;
        if (j0 < 1024) kb = kvm + ((size_t)bt * 1024 + j0) * 2048 + h * DHEAD;
        else           kb = kvl + ((size_t)bt * 64 + (j0 - 1024)) * 2048 + h * DHEAD;

        for (int idx = tid; idx < 512; idx += 256) {
            int r = idx >> 4;
            int c = (idx & 15) << 2;
            const float* src = kb + (size_t)r * 2048 + c;
            float4 kk = *(const float4*)(src);
            ks[r][c + 0] = kk.x; ks[r][c + 1] = kk.y; ks[r][c + 2] = kk.z; ks[r][c + 3] = kk.w;
            float4 vv = *(const float4*)(src + 1024);
            vs[r][c + 0] = vv.x; vs[r][c + 1] = vv.y; vs[r][c + 2] = vv.z; vs[r][c + 3] = vv.w;
        }
        __syncthreads();

        #pragma unroll
        for (int i = 0; i < 8; i++) {
            int qi = (w << 3) + i;
            float s = 0.f;
            #pragma unroll
            for (int d = 0; d < 64; ++d) s = fmaf(qs[qi][d], ks[lane][d], s);
            float cm = s;
            #pragma unroll
            for (int off = 16; off; off >>= 1)
                cm = fmaxf(cm, __shfl_xor_sync(0xffffffffu, cm, off));
            float mt = fmaxf(m[i], cm);
            float p  = __expf(s - mt);
            float psum = p;
            #pragma unroll
            for (int off = 16; off; off >>= 1)
                psum += __shfl_xor_sync(0xffffffffu, psum, off);
            float corr = __expf(m[i] - mt);
            l[i] = l[i] * corr + psum;
            m[i] = mt;
            o0[i] *= corr;
            o1[i] *= corr;
            ps[w][i][lane] = p;
        }
        __syncwarp();
        #pragma unroll
        for (int i = 0; i < 8; i++) {
            float a0 = o0[i], a1 = o1[i];
            #pragma unroll
            for (int jj = 0; jj < 32; jj++) {
                float p = ps[w][i][jj];
                a0 = fmaf(p, vs[jj][lane],      a0);
                a1 = fmaf(p, vs[jj][lane + 32], a1);
            }
            o0[i] = a0; o1[i] = a1;
        }
        __syncthreads();
    }

    #pragma unroll
    for (int i = 0; i < 8; i++) {
        float inv = 1.f / l[i];
        size_t row = (size_t)bt * 64 + (w << 3) + i;
        outp[row * INNERV + h * DHEAD + lane]      = tf32r(o0[i] * inv);
        outp[row * INNERV + h * DHEAD + lane + 32] = tf32r(o1[i] * inv);
    }
}

// ---------------------------------------------------------------------------
// Host orchestration
// ---------------------------------------------------------------------------
extern "C" void kernel_launch(void* const* d_in, const int* in_sizes, int n_in,
                              void* d_out, int out_size)
{
    const float* x       = (const float*)d_in[0];
    const float* latents = (const float*)d_in[1];
    const float* nm_g    = (const float*)d_in[2];
    const float* nm_b    = (const float*)d_in[3];
    const float* nl_g    = (const float*)d_in[4];
    const float* nl_b    = (const float*)d_in[5];
    const float* wq      = (const float*)d_in[6];
    const float* wkv     = (const float*)d_in[7];
    const float* wo      = (const float*)d_in[8];
    const float* ff_g    = (const float*)d_in[9];
    const float* ff_b    = (const float*)d_in[10];
    const float* w1      = (const float*)d_in[11];
    const float* w2      = (const float*)d_in[12];
    const float* fin_g   = (const float*)d_in[13];
    const float* fin_b   = (const float*)d_in[14];

    float *xhat, *kvm, *lat, *latn, *qb, *kvl, *attn, *ffh;
    float *wqT, *wkvT, *wkvTl, *woT, *w1T, *w2T, *kvbias;
    cudaGetSymbolAddress((void**)&xhat,  g_xhat);
    cudaGetSymbolAddress((void**)&kvm,   g_kvm);
    cudaGetSymbolAddress((void**)&lat,   g_lat);
    cudaGetSymbolAddress((void**)&latn,  g_latn);
    cudaGetSymbolAddress((void**)&qb,    g_qb);
    cudaGetSymbolAddress((void**)&kvl,   g_kvl);
    cudaGetSymbolAddress((void**)&attn,  g_attn);
    cudaGetSymbolAddress((void**)&ffh,   g_ffh);
    cudaGetSymbolAddress((void**)&wqT,   g_wqT);
    cudaGetSymbolAddress((void**)&wkvT,  g_wkvT);
    cudaGetSymbolAddress((void**)&wkvTl, g_wkvTl);
    cudaGetSymbolAddress((void**)&woT,   g_woT);
    cudaGetSymbolAddress((void**)&w1T,   g_w1T);
    cudaGetSymbolAddress((void**)&w2T,   g_w2T);
    cudaGetSymbolAddress((void**)&kvbias, g_kvbias);

    const int SMEM = 4 * 128 * PADK * 4;   // 73728 B
    cudaFuncSetAttribute(gemm_mma, cudaFuncAttributeMaxDynamicSharedMemorySize, SMEM);

    // precompute: transposed tf32 weights (+ media-LN fold) and KV bias rows
    for (int i = 0; i < NDEPTH; i++) {
        const float* wkv_i = wkv + (size_t)i * DIMV * 2 * INNERV;
        wtrans_kernel<<<dim3(2048 / 32, 1024 / 32), 256>>>(
            wkv_i, wkvT + (size_t)i * 2 * INNERV * DIMV, DIMV, 2 * INNERV,
            nm_g + (size_t)i * DIMV);
        wtrans_kernel<<<dim3(2048 / 32, 1024 / 32), 256>>>(
            wkv_i, wkvTl + (size_t)i * 2 * INNERV * DIMV, DIMV, 2 * INNERV, nullptr);
        bias_kernel<<<2048 / 256, 256>>>(
            nm_b + (size_t)i * DIMV, wkv_i, kvbias + (size_t)i * 2 * INNERV,
            DIMV, 2 * INNERV);
        wtrans_kernel<<<dim3(1024 / 32, 1024 / 32), 256>>>(
            wq + (size_t)i * DIMV * INNERV, wqT + (size_t)i * INNERV * DIMV,
            DIMV, INNERV, nullptr);
        wtrans_kernel<<<dim3(1024 / 32, 1024 / 32), 256>>>(
            wo + (size_t)i * INNERV * DIMV, woT + (size_t)i * DIMV * INNERV,
            INNERV, DIMV, nullptr);
        wtrans_kernel<<<dim3(4096 / 32, 1024 / 32), 256>>>(
            w1 + (size_t)i * DIMV * FFV, w1T + (size_t)i * FFV * DIMV,
            DIMV, FFV, nullptr);
        wtrans_kernel<<<dim3(1024 / 32, 4096 / 32), 256>>>(
            w2 + (size_t)i * FFV * DIMV, w2T + (size_t)i * DIMV * FFV,
            FFV, DIMV, nullptr);
    }

    init_lat_kernel<<<2048, 256>>>(latents, lat);
    // xhat = tf32( LN(x) ), no affine (folded into wkvT/kvbias)
    ln_kernel<<<BTV * MEDIA, 256>>>(x, xhat, nullptr, nullptr, 1);

    for (int i = 0; i < NDEPTH; i++) {
        const float* wkvT_i  = wkvT  + (size_t)i * 2 * INNERV * DIMV;
        const float* wkvTl_i = wkvTl + (size_t)i * 2 * INNERV * DIMV;
        const float* wqT_i   = wqT   + (size_t)i * INNERV * DIMV;
        const float* woT_i   = woT   + (size_t)i * DIMV * INNERV;
        const float* w1T_i   = w1T   + (size_t)i * FFV * DIMV;
        const float* w2T_i   = w2T   + (size_t)i * DIMV * FFV;
        const float* kvb_i   = kvbias + (size_t)i * 2 * INNERV;

        // media KV projection: [32768,1024]@[1024,2048] + bias row
        gemm_mma<<<dim3(16, 256), 256, SMEM>>>(xhat, wkvT_i, kvm,
            DIMV, DIMV, 2 * INNERV, kvb_i, nullptr, 0, 0);

        ln_kernel<<<BTV * NLAT, 256>>>(lat, latn,
            nl_g + (size_t)i * DIMV, nl_b + (size_t)i * DIMV, 1);
        gemm_mma<<<dim3(8, 16), 256, SMEM>>>(latn, wqT_i, qb,
            DIMV, DIMV, INNERV, nullptr, nullptr, 0, 0);
        gemm_mma<<<dim3(16, 16), 256, SMEM>>>(latn, wkvTl_i, kvl,
            DIMV, DIMV, 2 * INNERV, nullptr, nullptr, 0, 0);

        attn_kernel<<<BTV * NHEADS, 256>>>(qb, kvm, kvl, attn);

        gemm_mma<<<dim3(8, 16), 256, SMEM>>>(attn, woT_i, lat,
            INNERV, INNERV, DIMV, nullptr, lat, 0, 0);

        ln_kernel<<<BTV * NLAT, 256>>>(lat, latn,
            ff_g + (size_t)i * DIMV, ff_b + (size_t)i * DIMV, 1);
        gemm_mma<<<dim3(32, 16), 256, SMEM>>>(latn, w1T_i, ffh,
            DIMV, DIMV, FFV, nullptr, nullptr, 1, 1);
        gemm_mma<<<dim3(8, 16), 256, SMEM>>>(ffh, w2T_i, lat,
            FFV, FFV, DIMV, nullptr, lat, 0, 0);
    }

    ln_kernel<<<BTV * NLAT, 256>>>(lat, (float*)d_out, fin_g, fin_b, 0);
}